// round 8
// baseline (speedup 1.0000x reference)
#include <cuda_runtime.h>
#include <cuda_bf16.h>
#include <math.h>
#include <stdint.h>

// Problem constants
#define BATCH 8192
#define DIN   1025
#define HID   1024
#define NACT  1026
#define NHEAD 513
#define KSEQ  32

// Padded dims
#define KP1   1152   // DIN padded to mult of 128
#define KP2   1024   // HID (already mult of 128)
#define NACTP 1088   // NACT padded to mult of 64

// ---------------------------------------------------------------------------
// Scratch (allocation-free: __device__ globals)
// ---------------------------------------------------------------------------
__device__ int8_t g_qSh[(size_t)BATCH * KP1];
__device__ int8_t g_qSl[(size_t)BATCH * KP1];
__device__ int8_t g_qW0h[(size_t)HID * KP1];
__device__ int8_t g_qW0l[(size_t)HID * KP1];
__device__ int8_t g_qW1h[(size_t)HID * KP2];
__device__ int8_t g_qW1l[(size_t)HID * KP2];
__device__ int8_t g_qW2h[(size_t)NACTP * KP2];
__device__ int8_t g_qW2l[(size_t)NACTP * KP2];
__device__ int8_t g_qH0h[(size_t)BATCH * KP2];
__device__ int8_t g_qH0l[(size_t)BATCH * KP2];
__device__ int8_t g_qH1h[(size_t)BATCH * KP2];
__device__ int8_t g_qH1l[(size_t)BATCH * KP2];
__device__ float g_sS[BATCH];
__device__ float g_sH0[BATCH];
__device__ float g_sH1[BATCH];
__device__ float g_sW0[HID];
__device__ float g_sW1[HID];
__device__ float g_sW2[NACTP];
__device__ float g_h0f[(size_t)BATCH * HID];
__device__ float g_h1f[(size_t)BATCH * HID];
__device__ float g_logits[(size_t)BATCH * NACT];

// ---------------------------------------------------------------------------
// PTX helpers
// ---------------------------------------------------------------------------
__device__ __forceinline__ void ldsm_x4(uint32_t& r0, uint32_t& r1,
                                        uint32_t& r2, uint32_t& r3,
                                        const void* p)
{
    uint32_t a = (uint32_t)__cvta_generic_to_shared(p);
    asm volatile("ldmatrix.sync.aligned.m8n8.x4.shared.b16 {%0,%1,%2,%3}, [%4];"
                 : "=r"(r0), "=r"(r1), "=r"(r2), "=r"(r3) : "r"(a));
}

__device__ __forceinline__ void mma_s8(int* d, const uint32_t* a, const uint32_t* b)
{
    asm volatile(
        "mma.sync.aligned.m16n8k32.row.col.s32.s8.s8.s32 "
        "{%0,%1,%2,%3}, {%4,%5,%6,%7}, {%8,%9}, {%0,%1,%2,%3};"
        : "+r"(d[0]), "+r"(d[1]), "+r"(d[2]), "+r"(d[3])
        : "r"(a[0]), "r"(a[1]), "r"(a[2]), "r"(a[3]),
          "r"(b[0]), "r"(b[1]));
}

// ---------------------------------------------------------------------------
// Quantization prep kernels
// ---------------------------------------------------------------------------
// Per-column absmax of W [K,N] -> scale[Npad] = amax/127 (pad cols get tiny).
__global__ void __launch_bounds__(256)
colmax_W(const float* __restrict__ W, int K, int N, int Npad,
         float* __restrict__ scale)
{
    int col = blockIdx.x * 256 + threadIdx.x;
    if (col >= Npad) return;
    float m = 0.0f;
    if (col < N)
        for (int k = 0; k < K; k++)
            m = fmaxf(m, fabsf(W[(size_t)k * N + col]));
    scale[col] = fmaxf(m, 1e-20f) * (1.0f / 127.0f);
}

// Transpose + two-level quantize: W [K,N] fp32 -> qh/ql [Npad, Kpad] int8.
__global__ void __launch_bounds__(256)
quantT_W(const float* __restrict__ W, const float* __restrict__ scale,
         int8_t* __restrict__ qh, int8_t* __restrict__ ql,
         int K, int N, int Kpad)
{
    __shared__ float t[32][33];
    int n0 = blockIdx.x * 32, k0 = blockIdx.y * 32;
    int tx = threadIdx.x, ty = threadIdx.y;
    for (int j = ty; j < 32; j += 8) {
        int k = k0 + j, n = n0 + tx;
        t[j][tx] = (k < K && n < N) ? W[(size_t)k * N + n] : 0.0f;
    }
    __syncthreads();
    for (int j = ty; j < 32; j += 8) {
        int n = n0 + j, k = k0 + tx;
        float inv = 1.0f / scale[n];
        float x = t[tx][j];
        float tt = x * inv;
        float qhf = rintf(tt);
        float r = tt - qhf;
        float qlf = fminf(fmaxf(rintf(r * 256.0f), -128.0f), 127.0f);
        size_t o = (size_t)n * Kpad + k;
        qh[o] = (int8_t)(int)qhf;
        ql[o] = (int8_t)(int)qlf;
    }
}

// Per-row two-level quantize: src [rows, C] fp32 -> qh/ql [rows, Cpad] int8,
// scale[row] = rowmax/127.  One block per row.
__global__ void __launch_bounds__(256)
quant_rows(const float* __restrict__ src, int C, int Cpad,
           int8_t* __restrict__ qh, int8_t* __restrict__ ql,
           float* __restrict__ scale)
{
    __shared__ float red[256];
    const int row = blockIdx.x, tid = threadIdx.x;
    const float* p = src + (size_t)row * C;

    float m = 0.0f;
    for (int c = tid; c < C; c += 256) m = fmaxf(m, fabsf(p[c]));
    red[tid] = m;
    __syncthreads();
    for (int s = 128; s > 0; s >>= 1) {
        if (tid < s) red[tid] = fmaxf(red[tid], red[tid + s]);
        __syncthreads();
    }
    float amax = fmaxf(red[0], 1e-20f);
    float inv = 127.0f / amax;
    if (tid == 0) scale[row] = amax * (1.0f / 127.0f);

    char4* qh4 = (char4*)(qh + (size_t)row * Cpad);
    char4* ql4 = (char4*)(ql + (size_t)row * Cpad);
    for (int v = tid; v < Cpad / 4; v += 256) {
        int c = v * 4;
        char4 h4, l4;
        signed char* hp = (signed char*)&h4;
        signed char* lp = (signed char*)&l4;
#pragma unroll
        for (int j = 0; j < 4; j++) {
            float x = (c + j < C) ? p[c + j] : 0.0f;
            float tt = x * inv;
            float qhf = rintf(tt);
            float r = tt - qhf;
            float qlf = fminf(fmaxf(rintf(r * 256.0f), -128.0f), 127.0f);
            hp[j] = (signed char)(int)qhf;
            lp[j] = (signed char)(int)qlf;
        }
        qh4[v] = h4;
        ql4[v] = l4;
    }
}

// ---------------------------------------------------------------------------
// int8 two-level tensor-core GEMM.
//   C = act( (sA.qAh + sA.qAl/256) @ (sB.qBh + sB.qBl/256)^T + bias )
// acc_hh = qAh@qBh ; acc_x = qAh@qBl + qAl@qBh ; ll dropped.
// CTA 128x64 tile, BK=128, 256 threads = 8 warps (4M x 2N), warp tile 32x32.
// A: [M,Kp] K-major int8; B: [Npad,Kp] K-major int8 (pre-transposed weights).
// Single smem buffer, plain LDG/STS, 2 barriers/chunk, 2 CTAs/SM.
// ---------------------------------------------------------------------------
#define CTA_M 128
#define CTA_N 64
#define BK 128
#define ARS 144                        // A smem row stride bytes (128 + 16 pad)
#define BRS 144
#define SA_BYTES (128 * ARS)           // 18432 per tensor
#define SB_BYTES (64 * BRS)            // 9216 per tensor
#define GSMEM (2 * SA_BYTES + 2 * SB_BYTES)   // 55296 B

template <int OUT>
__global__ void __launch_bounds__(256, 2)
gemm_int8(const int8_t* __restrict__ Ah, const int8_t* __restrict__ Al,
          const float* __restrict__ sA, int lda,
          const int8_t* __restrict__ Bh, const int8_t* __restrict__ Bl,
          const float* __restrict__ sB, int ldb,
          const float* __restrict__ bias,
          float* __restrict__ C, int ldc, int Nvalid, int kIters)
{
    extern __shared__ int8_t smi[];
    int8_t* sAh = smi;
    int8_t* sAl = sAh + SA_BYTES;
    int8_t* sBh = sAl + SA_BYTES;
    int8_t* sBl = sBh + SB_BYTES;

    const int tid = threadIdx.x, lane = tid & 31, wid = tid >> 5;
    const int warpRow = (wid & 3) * 32;     // 4 warps along M
    const int warpCol = (wid >> 2) * 32;    // 2 warps along N
    const int bm = blockIdx.y * CTA_M, bn = blockIdx.x * CTA_N;

    int accHH[2][4][4], accX[2][4][4];
#pragma unroll
    for (int i = 0; i < 2; i++)
#pragma unroll
        for (int j = 0; j < 4; j++)
#pragma unroll
            for (int f = 0; f < 4; f++) { accHH[i][j][f] = 0; accX[i][j][f] = 0; }

    // ldmatrix lane addressing (b16 view of int8 pairs)
    const int lm = lane >> 3, lr = lane & 7;
    const int rowOff = (lm & 1) * 8 + lr;       // row within 16-row window
    const int colOffBytes = (lm >> 1) * 16;     // 0 or 16 bytes (8 b16)

    for (int kt = 0; kt < kIters; kt++) {
        const int k0 = kt * BK;

        // A: 128 rows x 128 B = 1024 uint4; 4/thread.
#pragma unroll
        for (int v = 0; v < 4; v++) {
            int idx = v * 256 + tid;
            int ar = idx >> 3, ab = (idx & 7) << 4;
            const size_t ga = (size_t)(bm + ar) * lda + k0 + ab;
            *(uint4*)(sAh + ar * ARS + ab) = *(const uint4*)(Ah + ga);
            *(uint4*)(sAl + ar * ARS + ab) = *(const uint4*)(Al + ga);
        }
        // B: 64 rows x 128 B = 512 uint4; 2/thread.
#pragma unroll
        for (int v = 0; v < 2; v++) {
            int idx = v * 256 + tid;
            int br = idx >> 3, bb = (idx & 7) << 4;
            const size_t gb = (size_t)(bn + br) * ldb + k0 + bb;
            *(uint4*)(sBh + br * BRS + bb) = *(const uint4*)(Bh + gb);
            *(uint4*)(sBl + br * BRS + bb) = *(const uint4*)(Bl + gb);
        }
        __syncthreads();

#pragma unroll
        for (int ks = 0; ks < BK / 32; ks++) {
            // B fragments: 2 x4-ldsm per tensor cover 32 n rows -> 4 n8-groups.
            uint32_t bqh[4][2], bql[4][2];
#pragma unroll
            for (int njp = 0; njp < 2; njp++) {
                const int8_t* pb = sBh + (warpCol + njp * 16 + rowOff) * BRS
                                 + ks * 32 + colOffBytes;
                uint32_t r0, r1, r2, r3;
                ldsm_x4(r0, r1, r2, r3, pb);
                bqh[njp * 2 + 0][0] = r0; bqh[njp * 2 + 0][1] = r2;
                bqh[njp * 2 + 1][0] = r1; bqh[njp * 2 + 1][1] = r3;
                ldsm_x4(r0, r1, r2, r3, pb + SB_BYTES);   // sBl
                bql[njp * 2 + 0][0] = r0; bql[njp * 2 + 0][1] = r2;
                bql[njp * 2 + 1][0] = r1; bql[njp * 2 + 1][1] = r3;
            }
            // A fragments per mi; 3 products into 2 accumulators.
#pragma unroll
            for (int mi = 0; mi < 2; mi++) {
                const int8_t* pa = sAh + (warpRow + mi * 16 + rowOff) * ARS
                                 + ks * 32 + colOffBytes;
                uint32_t ah[4], al[4];
                ldsm_x4(ah[0], ah[1], ah[2], ah[3], pa);
                ldsm_x4(al[0], al[1], al[2], al[3], pa + SA_BYTES);
#pragma unroll
                for (int nj = 0; nj < 4; nj++) {
                    mma_s8(accHH[mi][nj], ah, bqh[nj]);
                    mma_s8(accX[mi][nj],  ah, bql[nj]);
                    mma_s8(accX[mi][nj],  al, bqh[nj]);
                }
            }
        }
        __syncthreads();
    }

    // Epilogue: dequant + bias (+ReLU) -> fp32, coalesced float2 stores.
    const int gid = lane >> 2, tg = lane & 3;
#pragma unroll
    for (int mi = 0; mi < 2; mi++) {
#pragma unroll
        for (int nj = 0; nj < 4; nj++) {
            int col = bn + warpCol + nj * 8 + tg * 2;
            bool ok = (OUT == 0) || (col + 1 < Nvalid);   // pairs never straddle
            float sb0 = 0.f, sb1 = 0.f, bv0 = 0.f, bv1 = 0.f;
            if (ok) { sb0 = sB[col]; sb1 = sB[col + 1];
                      bv0 = bias[col]; bv1 = bias[col + 1]; }
#pragma unroll
            for (int half = 0; half < 2; half++) {
                int row = bm + warpRow + mi * 16 + gid + half * 8;
                float sa = sA[row];
                float f0 = fmaf((float)accX[mi][nj][half * 2 + 0], 0.00390625f,
                                (float)accHH[mi][nj][half * 2 + 0]);
                float f1 = fmaf((float)accX[mi][nj][half * 2 + 1], 0.00390625f,
                                (float)accHH[mi][nj][half * 2 + 1]);
                float v0 = sa * sb0 * f0 + bv0;
                float v1 = sa * sb1 * f1 + bv1;
                if (OUT == 0) {
                    v0 = fmaxf(v0, 0.0f);
                    v1 = fmaxf(v1, 0.0f);
                    float2 v; v.x = v0; v.y = v1;
                    *(float2*)&C[(size_t)row * ldc + col] = v;
                } else if (ok) {
                    float2 v; v.x = v0; v.y = v1;
                    *(float2*)&C[(size_t)row * ldc + col] = v;
                }
            }
        }
    }
}

// ---------------------------------------------------------------------------
// Sampler: incremental log-softmax-without-replacement
// ---------------------------------------------------------------------------
__global__ void __launch_bounds__(64)
sampler_kernel(const float* __restrict__ logits,
               const int* __restrict__ idxR, const int* __restrict__ lenR,
               const int* __restrict__ idxS, const int* __restrict__ lenS,
               float* __restrict__ out)
{
    const int b = blockIdx.x;
    const int w = threadIdx.x >> 5;
    const int lane = threadIdx.x & 31;

    const float* lrow = logits + (size_t)b * NACT + w * NHEAD;
    const int* sidx = (w == 0 ? idxR : idxS) + (size_t)b * KSEQ;
    const int slen = (w == 0 ? lenR : lenS)[b];

    float m = -INFINITY;
    for (int i = lane; i < NHEAD; i += 32) m = fmaxf(m, lrow[i]);
#pragma unroll
    for (int off = 16; off > 0; off >>= 1)
        m = fmaxf(m, __shfl_xor_sync(0xFFFFFFFFu, m, off));

    float S1 = 0.0f, S2 = 0.0f;
    for (int i = lane; i < NHEAD; i += 32) {
        float l = lrow[i] - m;
        float e = expf(l);
        S1 += e;
        S2 += l * e;
    }
#pragma unroll
    for (int off = 16; off > 0; off >>= 1) {
        S1 += __shfl_xor_sync(0xFFFFFFFFu, S1, off);
        S2 += __shfl_xor_sync(0xFFFFFFFFu, S2, off);
    }

    __shared__ float sh[4];
    if (lane == 0) {
        float logp = 0.0f, ent = 0.0f;
        for (int t = 0; t < slen; t++) {
            float lS1 = logf(S1);
            ent += lS1 - S2 / S1;
            int id = sidx[t];
            if (id >= 0) {
                float l = lrow[id] - m;
                logp += l - lS1;
                float e = expf(l);
                S1 -= e;
                S2 -= l * e;
            }
        }
        sh[w * 2 + 0] = logp;
        sh[w * 2 + 1] = ent;
    }
    __syncthreads();
    if (threadIdx.x == 0) {
        out[b]         = sh[0] + sh[2];
        out[BATCH + b] = sh[1] + sh[3];
    }
}

// ---------------------------------------------------------------------------
// Launch
// ---------------------------------------------------------------------------
extern "C" void kernel_launch(void* const* d_in, const int* in_sizes, int n_in,
                              void* d_out, int out_size)
{
    const float* state = (const float*)d_in[0];
    const float* W0    = (const float*)d_in[1];
    const float* b0    = (const float*)d_in[2];
    const float* W1    = (const float*)d_in[3];
    const float* b1    = (const float*)d_in[4];
    const float* W2    = (const float*)d_in[5];
    const float* b2    = (const float*)d_in[6];
    const int* seq_idx_R = (const int*)d_in[7];
    const int* seq_len_R = (const int*)d_in[8];
    const int* seq_idx_S = (const int*)d_in[9];
    const int* seq_len_S = (const int*)d_in[10];
    float* out = (float*)d_out;

    int8_t *qSh, *qSl, *qW0h, *qW0l, *qW1h, *qW1l, *qW2h, *qW2l;
    int8_t *qH0h, *qH0l, *qH1h, *qH1l;
    float *sS, *sH0, *sH1, *sW0, *sW1, *sW2, *h0f, *h1f, *lg;
    cudaGetSymbolAddress((void**)&qSh, g_qSh);
    cudaGetSymbolAddress((void**)&qSl, g_qSl);
    cudaGetSymbolAddress((void**)&qW0h, g_qW0h);
    cudaGetSymbolAddress((void**)&qW0l, g_qW0l);
    cudaGetSymbolAddress((void**)&qW1h, g_qW1h);
    cudaGetSymbolAddress((void**)&qW1l, g_qW1l);
    cudaGetSymbolAddress((void**)&qW2h, g_qW2h);
    cudaGetSymbolAddress((void**)&qW2l, g_qW2l);
    cudaGetSymbolAddress((void**)&qH0h, g_qH0h);
    cudaGetSymbolAddress((void**)&qH0l, g_qH0l);
    cudaGetSymbolAddress((void**)&qH1h, g_qH1h);
    cudaGetSymbolAddress((void**)&qH1l, g_qH1l);
    cudaGetSymbolAddress((void**)&sS, g_sS);
    cudaGetSymbolAddress((void**)&sH0, g_sH0);
    cudaGetSymbolAddress((void**)&sH1, g_sH1);
    cudaGetSymbolAddress((void**)&sW0, g_sW0);
    cudaGetSymbolAddress((void**)&sW1, g_sW1);
    cudaGetSymbolAddress((void**)&sW2, g_sW2);
    cudaGetSymbolAddress((void**)&h0f, g_h0f);
    cudaGetSymbolAddress((void**)&h1f, g_h1f);
    cudaGetSymbolAddress((void**)&lg, g_logits);

    cudaFuncSetAttribute(gemm_int8<0>, cudaFuncAttributeMaxDynamicSharedMemorySize, GSMEM);
    cudaFuncSetAttribute(gemm_int8<1>, cudaFuncAttributeMaxDynamicSharedMemorySize, GSMEM);

    // Weight quantization (colmax -> transpose+quantize)
    colmax_W<<<(HID + 255) / 256, 256>>>(W0, DIN, HID, HID, sW0);
    colmax_W<<<(HID + 255) / 256, 256>>>(W1, HID, HID, HID, sW1);
    colmax_W<<<(NACTP + 255) / 256, 256>>>(W2, HID, NACT, NACTP, sW2);
    quantT_W<<<dim3(HID / 32, KP1 / 32), dim3(32, 8)>>>(W0, sW0, qW0h, qW0l, DIN, HID, KP1);
    quantT_W<<<dim3(HID / 32, KP2 / 32), dim3(32, 8)>>>(W1, sW1, qW1h, qW1l, HID, HID, KP2);
    quantT_W<<<dim3(NACTP / 32, KP2 / 32), dim3(32, 8)>>>(W2, sW2, qW2h, qW2l, HID, NACT, KP2);

    // Input quantization
    quant_rows<<<BATCH, 256>>>(state, DIN, KP1, qSh, qSl, sS);

    dim3 blk(256);
    dim3 g12(HID / CTA_N, BATCH / CTA_M);     // (16, 64)
    dim3 g3(NACTP / CTA_N, BATCH / CTA_M);    // (17, 64)

    // Layer 0
    gemm_int8<0><<<g12, blk, GSMEM>>>(qSh, qSl, sS, KP1, qW0h, qW0l, sW0, KP1,
                                      b0, h0f, HID, HID, KP1 / BK);
    quant_rows<<<BATCH, 256>>>(h0f, HID, KP2, qH0h, qH0l, sH0);
    // Layer 1
    gemm_int8<0><<<g12, blk, GSMEM>>>(qH0h, qH0l, sH0, KP2, qW1h, qW1l, sW1, KP2,
                                      b1, h1f, HID, HID, KP2 / BK);
    quant_rows<<<BATCH, 256>>>(h1f, HID, KP2, qH1h, qH1l, sH1);
    // Layer 2 (logits)
    gemm_int8<1><<<g3, blk, GSMEM>>>(qH1h, qH1l, sH1, KP2, qW2h, qW2l, sW2, KP2,
                                     b2, lg, NACT, NACT, KP2 / BK);

    sampler_kernel<<<BATCH, 64>>>(lg, seq_idx_R, seq_len_R,
                                  seq_idx_S, seq_len_S, out);
}

// round 9
// speedup vs baseline: 2.7719x; 2.7719x over previous
#include <cuda_runtime.h>
#include <cuda_bf16.h>
#include <math.h>
#include <stdint.h>

// Problem constants
#define BATCH 8192
#define DIN   1025
#define HID   1024
#define NACT  1026
#define NHEAD 513
#define KSEQ  32

// Padded dims (K padded to mult of 64 for BK=64 chunks)
#define DINP  1088
#define NACTP 1152

// ---------------------------------------------------------------------------
// Scratch (allocation-free: __device__ globals)
// ---------------------------------------------------------------------------
__device__ __nv_bfloat16 g_Shi[(size_t)BATCH * DINP];
__device__ __nv_bfloat16 g_Slo[(size_t)BATCH * DINP];
__device__ __nv_bfloat16 g_W0h[(size_t)DINP * HID];
__device__ __nv_bfloat16 g_W0l[(size_t)DINP * HID];
__device__ __nv_bfloat16 g_W1h[(size_t)HID * HID];
__device__ __nv_bfloat16 g_W1l[(size_t)HID * HID];
__device__ __nv_bfloat16 g_W2h[(size_t)HID * NACTP];
__device__ __nv_bfloat16 g_W2l[(size_t)HID * NACTP];
__device__ __nv_bfloat16 g_H0h[(size_t)BATCH * HID];
__device__ __nv_bfloat16 g_H0l[(size_t)BATCH * HID];
__device__ __nv_bfloat16 g_H1h[(size_t)BATCH * HID];
__device__ __nv_bfloat16 g_H1l[(size_t)BATCH * HID];
__device__ float g_logits[(size_t)BATCH * NACT];

// ---------------------------------------------------------------------------
// Split/pad: fp32 [R,C] -> bf16 hi/lo [Rpad, Cpad], zero outside [R,C].
// ---------------------------------------------------------------------------
__global__ void split_pad_kernel(const float* __restrict__ src,
                                 __nv_bfloat16* __restrict__ hi,
                                 __nv_bfloat16* __restrict__ lo,
                                 int R, int C, int Rpad, int Cpad)
{
    size_t total = (size_t)Rpad * Cpad;
    for (size_t idx = (size_t)blockIdx.x * blockDim.x + threadIdx.x;
         idx < total; idx += (size_t)gridDim.x * blockDim.x) {
        int r = (int)(idx / Cpad);
        int c = (int)(idx % Cpad);
        float v = 0.0f;
        if (r < R && c < C) v = src[(size_t)r * C + c];
        __nv_bfloat16 h = __float2bfloat16(v);
        __nv_bfloat16 l = __float2bfloat16(v - __bfloat162float(h));
        hi[idx] = h;
        lo[idx] = l;
    }
}

// ---------------------------------------------------------------------------
// PTX helpers
// ---------------------------------------------------------------------------
__device__ __forceinline__ void ldsm_x4(uint32_t& r0, uint32_t& r1,
                                        uint32_t& r2, uint32_t& r3,
                                        const void* p)
{
    uint32_t a = (uint32_t)__cvta_generic_to_shared(p);
    asm volatile("ldmatrix.sync.aligned.m8n8.x4.shared.b16 {%0,%1,%2,%3}, [%4];"
                 : "=r"(r0), "=r"(r1), "=r"(r2), "=r"(r3) : "r"(a));
}

__device__ __forceinline__ void ldsm_x4_trans(uint32_t& r0, uint32_t& r1,
                                              uint32_t& r2, uint32_t& r3,
                                              const void* p)
{
    uint32_t a = (uint32_t)__cvta_generic_to_shared(p);
    asm volatile("ldmatrix.sync.aligned.m8n8.x4.trans.shared.b16 {%0,%1,%2,%3}, [%4];"
                 : "=r"(r0), "=r"(r1), "=r"(r2), "=r"(r3) : "r"(a));
}

// NOTE: non-volatile on purpose — pure register op, lets ptxas schedule/interleave.
__device__ __forceinline__ void mma16816(float* d, const uint32_t* a, const uint32_t* b)
{
    asm("mma.sync.aligned.m16n8k16.row.col.f32.bf16.bf16.f32 "
        "{%0,%1,%2,%3}, {%4,%5,%6,%7}, {%8,%9}, {%0,%1,%2,%3};"
        : "+f"(d[0]), "+f"(d[1]), "+f"(d[2]), "+f"(d[3])
        : "r"(a[0]), "r"(a[1]), "r"(a[2]), "r"(a[3]),
          "r"(b[0]), "r"(b[1]));
}

// ---------------------------------------------------------------------------
// bf16-split tensor-core GEMM (single buffer, plain LDG/STS, 2 barriers per
// K-chunk; 2 CTAs/SM provide load/compute overlap).
//   C = act( (Ahi+Alo) @ (Bhi+Blo) + bias ),  lo*lo product dropped.
// 128x128 CTA tile, BK=64, 256 threads = 8 warps (2x4), warp tile 64x32.
// mma issue order: per mi, hh over all nj, then hl, then lh -> dependent ops
// on the same accumulator are 4 mma apart (hides HMMA RAW latency).
// ---------------------------------------------------------------------------
#define GBM 128
#define GBN 128
#define GBK 64
#define APAD 72    // A smem row stride (halves): 144B rows, conflict-free ldsm
#define BPAD 136   // B smem row stride (halves): 272B rows, conflict-free ldsm
#define A_HALVES (GBM * APAD)                 // 9216 per tensor
#define B_HALVES (GBK * BPAD)                 // 8704 per tensor
#define GEMM_SMEM_BYTES ((2 * A_HALVES + 2 * B_HALVES) * 2)  // 71680 B

template <int OUT>
__global__ void __launch_bounds__(256, 2)
gemm_bf16_split(const __nv_bfloat16* __restrict__ Ahi,
                const __nv_bfloat16* __restrict__ Alo, int lda,
                const __nv_bfloat16* __restrict__ Bhi,
                const __nv_bfloat16* __restrict__ Blo, int ldb,
                const float* __restrict__ bias,
                __nv_bfloat16* __restrict__ Chi,
                __nv_bfloat16* __restrict__ Clo,
                float* __restrict__ Cf, int ldc, int Nvalid,
                int kIters)
{
    extern __shared__ __nv_bfloat16 sm[];
    __nv_bfloat16* sAh = sm;
    __nv_bfloat16* sAl = sAh + A_HALVES;
    __nv_bfloat16* sBh = sAl + A_HALVES;
    __nv_bfloat16* sBl = sBh + B_HALVES;

    const int tid  = threadIdx.x;
    const int lane = tid & 31;
    const int wid  = tid >> 5;
    const int warpRow = (wid & 1) * 64;
    const int warpCol = (wid >> 1) * 32;
    const int bm = blockIdx.y * GBM;
    const int bn = blockIdx.x * GBN;

    float acc[4][4][4];
#pragma unroll
    for (int i = 0; i < 4; i++)
#pragma unroll
        for (int j = 0; j < 4; j++)
#pragma unroll
            for (int f = 0; f < 4; f++) acc[i][j][f] = 0.0f;

    // ldmatrix lane addressing
    const int lm  = lane >> 3;
    const int lr  = lane & 7;
    const int aRowOff = (lm & 1) * 8 + lr;
    const int aColOff = (lm >> 1) * 8;
    const int bRowOff = (lm & 1) * 8 + lr;
    const int bColOff = (lm >> 1) * 8;

    for (int kt = 0; kt < kIters; kt++) {
        const int k0 = kt * GBK;

        // Load A: 128 rows x 64 halves = 1024 uint4 per tensor; 4/thread.
        // B: 64 rows x 128 halves = 1024 uint4 per tensor; 4/thread.
#pragma unroll
        for (int v = 0; v < 4; v++) {
            int idx = v * 256 + tid;
            int ar = idx >> 3, ak = (idx & 7) << 3;
            int br = idx >> 4, bn8 = (idx & 15) << 3;
            const size_t ga = (size_t)(bm + ar) * lda + k0 + ak;
            const size_t gb = (size_t)(k0 + br) * ldb + bn + bn8;
            *(uint4*)(sAh + ar * APAD + ak) = *(const uint4*)(Ahi + ga);
            *(uint4*)(sAl + ar * APAD + ak) = *(const uint4*)(Alo + ga);
            *(uint4*)(sBh + br * BPAD + bn8) = *(const uint4*)(Bhi + gb);
            *(uint4*)(sBl + br * BPAD + bn8) = *(const uint4*)(Blo + gb);
        }
        __syncthreads();

#pragma unroll
        for (int ks = 0; ks < GBK; ks += 16) {
            // B fragments for this ks (held across the mi loop)
            uint32_t bhi[4][2], blo[4][2];
#pragma unroll
            for (int ni = 0; ni < 2; ni++) {
                const __nv_bfloat16* pb = sBh + (ks + bRowOff) * BPAD
                                        + warpCol + ni * 16 + bColOff;
                uint32_t r0, r1, r2, r3;
                ldsm_x4_trans(r0, r1, r2, r3, pb);
                bhi[ni * 2 + 0][0] = r0; bhi[ni * 2 + 0][1] = r1;
                bhi[ni * 2 + 1][0] = r2; bhi[ni * 2 + 1][1] = r3;
                // sBl lives exactly B_HALVES elements after sBh
                ldsm_x4_trans(r0, r1, r2, r3, pb + B_HALVES);
                blo[ni * 2 + 0][0] = r0; blo[ni * 2 + 0][1] = r1;
                blo[ni * 2 + 1][0] = r2; blo[ni * 2 + 1][1] = r3;
            }
            // A fragments per mi (small live set -> fits 128 regs at occ 2).
            // Issue order: hh x4, hl x4, lh x4 -> same-acc dependency distance 4.
#pragma unroll
            for (int mi = 0; mi < 4; mi++) {
                const int row = warpRow + mi * 16 + aRowOff;
                uint32_t ahi[4], alo[4];
                ldsm_x4(ahi[0], ahi[1], ahi[2], ahi[3],
                        sAh + row * APAD + ks + aColOff);
                ldsm_x4(alo[0], alo[1], alo[2], alo[3],
                        sAl + row * APAD + ks + aColOff);
#pragma unroll
                for (int nj = 0; nj < 4; nj++)
                    mma16816(acc[mi][nj], ahi, bhi[nj]);
#pragma unroll
                for (int nj = 0; nj < 4; nj++)
                    mma16816(acc[mi][nj], ahi, blo[nj]);
#pragma unroll
                for (int nj = 0; nj < 4; nj++)
                    mma16816(acc[mi][nj], alo, bhi[nj]);
            }
        }
        __syncthreads();
    }

    // Epilogue: c-frag layout -> bias + act -> coalesced stores
    const int gid = lane >> 2;
    const int tg  = lane & 3;
#pragma unroll
    for (int mi = 0; mi < 4; mi++) {
#pragma unroll
        for (int nj = 0; nj < 4; nj++) {
            int col = bn + warpCol + nj * 8 + tg * 2;
            float bv0 = 0.0f, bv1 = 0.0f;
            if (OUT == 0 || col + 1 < Nvalid) {
                bv0 = bias[col];
                bv1 = bias[col + 1];
            }
#pragma unroll
            for (int half = 0; half < 2; half++) {
                int row = bm + warpRow + mi * 16 + gid + half * 8;
                float v0 = acc[mi][nj][half * 2 + 0] + bv0;
                float v1 = acc[mi][nj][half * 2 + 1] + bv1;
                if (OUT == 0) {
                    v0 = fmaxf(v0, 0.0f);
                    v1 = fmaxf(v1, 0.0f);
                    __nv_bfloat16 h0 = __float2bfloat16(v0);
                    __nv_bfloat16 h1 = __float2bfloat16(v1);
                    __nv_bfloat162 hp; hp.x = h0; hp.y = h1;
                    __nv_bfloat162 lp;
                    lp.x = __float2bfloat16(v0 - __bfloat162float(h0));
                    lp.y = __float2bfloat16(v1 - __bfloat162float(h1));
                    *(__nv_bfloat162*)&Chi[(size_t)row * ldc + col] = hp;
                    *(__nv_bfloat162*)&Clo[(size_t)row * ldc + col] = lp;
                } else {
                    if (col + 1 < Nvalid) {
                        float2 v; v.x = v0; v.y = v1;
                        *(float2*)&Cf[(size_t)row * ldc + col] = v;
                    }
                }
            }
        }
    }
}

// ---------------------------------------------------------------------------
// Sampler: incremental log-softmax-without-replacement
// ---------------------------------------------------------------------------
__global__ void __launch_bounds__(64)
sampler_kernel(const float* __restrict__ logits,
               const int* __restrict__ idxR, const int* __restrict__ lenR,
               const int* __restrict__ idxS, const int* __restrict__ lenS,
               float* __restrict__ out)
{
    const int b = blockIdx.x;
    const int w = threadIdx.x >> 5;
    const int lane = threadIdx.x & 31;

    const float* lrow = logits + (size_t)b * NACT + w * NHEAD;
    const int* sidx = (w == 0 ? idxR : idxS) + (size_t)b * KSEQ;
    const int slen = (w == 0 ? lenR : lenS)[b];

    float m = -INFINITY;
    for (int i = lane; i < NHEAD; i += 32) m = fmaxf(m, lrow[i]);
#pragma unroll
    for (int off = 16; off > 0; off >>= 1)
        m = fmaxf(m, __shfl_xor_sync(0xFFFFFFFFu, m, off));

    float S1 = 0.0f, S2 = 0.0f;
    for (int i = lane; i < NHEAD; i += 32) {
        float l = lrow[i] - m;
        float e = expf(l);
        S1 += e;
        S2 += l * e;
    }
#pragma unroll
    for (int off = 16; off > 0; off >>= 1) {
        S1 += __shfl_xor_sync(0xFFFFFFFFu, S1, off);
        S2 += __shfl_xor_sync(0xFFFFFFFFu, S2, off);
    }

    __shared__ float sh[4];
    if (lane == 0) {
        float logp = 0.0f, ent = 0.0f;
        for (int t = 0; t < slen; t++) {
            float lS1 = logf(S1);
            ent += lS1 - S2 / S1;
            int id = sidx[t];
            if (id >= 0) {
                float l = lrow[id] - m;
                logp += l - lS1;
                float e = expf(l);
                S1 -= e;
                S2 -= l * e;
            }
        }
        sh[w * 2 + 0] = logp;
        sh[w * 2 + 1] = ent;
    }
    __syncthreads();
    if (threadIdx.x == 0) {
        out[b]         = sh[0] + sh[2];
        out[BATCH + b] = sh[1] + sh[3];
    }
}

// ---------------------------------------------------------------------------
// Launch
// ---------------------------------------------------------------------------
extern "C" void kernel_launch(void* const* d_in, const int* in_sizes, int n_in,
                              void* d_out, int out_size)
{
    const float* state = (const float*)d_in[0];
    const float* W0    = (const float*)d_in[1];
    const float* b0    = (const float*)d_in[2];
    const float* W1    = (const float*)d_in[3];
    const float* b1    = (const float*)d_in[4];
    const float* W2    = (const float*)d_in[5];
    const float* b2    = (const float*)d_in[6];
    const int* seq_idx_R = (const int*)d_in[7];
    const int* seq_len_R = (const int*)d_in[8];
    const int* seq_idx_S = (const int*)d_in[9];
    const int* seq_len_S = (const int*)d_in[10];
    float* out = (float*)d_out;

    __nv_bfloat16 *Shi, *Slo, *W0h, *W0l, *W1h, *W1l, *W2h, *W2l;
    __nv_bfloat16 *H0h, *H0l, *H1h, *H1l;
    float* lg;
    cudaGetSymbolAddress((void**)&Shi, g_Shi);
    cudaGetSymbolAddress((void**)&Slo, g_Slo);
    cudaGetSymbolAddress((void**)&W0h, g_W0h);
    cudaGetSymbolAddress((void**)&W0l, g_W0l);
    cudaGetSymbolAddress((void**)&W1h, g_W1h);
    cudaGetSymbolAddress((void**)&W1l, g_W1l);
    cudaGetSymbolAddress((void**)&W2h, g_W2h);
    cudaGetSymbolAddress((void**)&W2l, g_W2l);
    cudaGetSymbolAddress((void**)&H0h, g_H0h);
    cudaGetSymbolAddress((void**)&H0l, g_H0l);
    cudaGetSymbolAddress((void**)&H1h, g_H1h);
    cudaGetSymbolAddress((void**)&H1l, g_H1l);
    cudaGetSymbolAddress((void**)&lg, g_logits);

    cudaFuncSetAttribute(gemm_bf16_split<0>, cudaFuncAttributeMaxDynamicSharedMemorySize, GEMM_SMEM_BYTES);
    cudaFuncSetAttribute(gemm_bf16_split<1>, cudaFuncAttributeMaxDynamicSharedMemorySize, GEMM_SMEM_BYTES);

    // Split + pad inputs/weights to bf16 hi/lo
    split_pad_kernel<<<2048, 256>>>(state, Shi, Slo, BATCH, DIN, BATCH, DINP);
    split_pad_kernel<<<1024, 256>>>(W0, W0h, W0l, DIN, HID, DINP, HID);
    split_pad_kernel<<<1024, 256>>>(W1, W1h, W1l, HID, HID, HID, HID);
    split_pad_kernel<<<1024, 256>>>(W2, W2h, W2l, HID, NACT, HID, NACTP);

    dim3 blk(256);
    dim3 g1(HID / GBN, BATCH / GBM);     // (8, 64)
    dim3 g3(NACTP / GBN, BATCH / GBM);   // (9, 64)

    gemm_bf16_split<0><<<g1, blk, GEMM_SMEM_BYTES>>>(Shi, Slo, DINP, W0h, W0l, HID, b0,
                                                     H0h, H0l, nullptr, HID, HID, DINP / GBK);
    gemm_bf16_split<0><<<g1, blk, GEMM_SMEM_BYTES>>>(H0h, H0l, HID, W1h, W1l, HID, b1,
                                                     H1h, H1l, nullptr, HID, HID, HID / GBK);
    gemm_bf16_split<1><<<g3, blk, GEMM_SMEM_BYTES>>>(H1h, H1l, HID, W2h, W2l, NACTP, b2,
                                                     nullptr, nullptr, lg, NACT, NACT, HID / GBK);

    sampler_kernel<<<BATCH, 64>>>(lg, seq_idx_R, seq_len_R,
                                  seq_idx_S, seq_len_S, out);
}

// round 10
// speedup vs baseline: 5.4239x; 1.9568x over previous
#include <cuda_runtime.h>
#include <cuda_fp16.h>
#include <math.h>
#include <stdint.h>

// Problem constants
#define BATCH 8192
#define DIN   1025
#define HID   1024
#define NACT  1026
#define NHEAD 513
#define KSEQ  32

// Padded dims (K and N padded to mult of 128)
#define KP1   1152   // DIN -> 1152
#define NACTP 1152   // NACT -> 1152

// ---------------------------------------------------------------------------
// Scratch (allocation-free: __device__ globals), all fp16 single precision-level
// ---------------------------------------------------------------------------
__device__ __half g_S [(size_t)BATCH * KP1];
__device__ __half g_W0[(size_t)KP1 * HID];
__device__ __half g_W1[(size_t)HID * HID];
__device__ __half g_W2[(size_t)HID * NACTP];
__device__ __half g_H0[(size_t)BATCH * HID];
__device__ __half g_H1[(size_t)BATCH * HID];
__device__ float  g_logits[(size_t)BATCH * NACT];

// ---------------------------------------------------------------------------
// Pad/convert: fp32 [R,C] -> fp16 [Rpad, Cpad], zero outside [R,C].
// ---------------------------------------------------------------------------
__global__ void pad_half_kernel(const float* __restrict__ src,
                                __half* __restrict__ dst,
                                int R, int C, int Rpad, int Cpad)
{
    size_t total = (size_t)Rpad * Cpad;
    for (size_t idx = (size_t)blockIdx.x * blockDim.x + threadIdx.x;
         idx < total; idx += (size_t)gridDim.x * blockDim.x) {
        int r = (int)(idx / Cpad);
        int c = (int)(idx % Cpad);
        float v = 0.0f;
        if (r < R && c < C) v = src[(size_t)r * C + c];
        dst[idx] = __float2half(v);
    }
}

// ---------------------------------------------------------------------------
// PTX helpers
// ---------------------------------------------------------------------------
__device__ __forceinline__ void ldsm_x4(uint32_t& r0, uint32_t& r1,
                                        uint32_t& r2, uint32_t& r3,
                                        const void* p)
{
    uint32_t a = (uint32_t)__cvta_generic_to_shared(p);
    asm volatile("ldmatrix.sync.aligned.m8n8.x4.shared.b16 {%0,%1,%2,%3}, [%4];"
                 : "=r"(r0), "=r"(r1), "=r"(r2), "=r"(r3) : "r"(a));
}

__device__ __forceinline__ void ldsm_x4_trans(uint32_t& r0, uint32_t& r1,
                                              uint32_t& r2, uint32_t& r3,
                                              const void* p)
{
    uint32_t a = (uint32_t)__cvta_generic_to_shared(p);
    asm volatile("ldmatrix.sync.aligned.m8n8.x4.trans.shared.b16 {%0,%1,%2,%3}, [%4];"
                 : "=r"(r0), "=r"(r1), "=r"(r2), "=r"(r3) : "r"(a));
}

__device__ __forceinline__ void mma16816(float* d, const uint32_t* a, const uint32_t* b)
{
    asm("mma.sync.aligned.m16n8k16.row.col.f32.f16.f16.f32 "
        "{%0,%1,%2,%3}, {%4,%5,%6,%7}, {%8,%9}, {%0,%1,%2,%3};"
        : "+f"(d[0]), "+f"(d[1]), "+f"(d[2]), "+f"(d[3])
        : "r"(a[0]), "r"(a[1]), "r"(a[2]), "r"(a[3]),
          "r"(b[0]), "r"(b[1]));
}

// ---------------------------------------------------------------------------
// fp16 tensor-core GEMM (single smem buffer, plain LDG/STS, 2 barriers per
// K-chunk; 2 CTAs/SM provide load/compute overlap).
//   C = act( A @ B + bias ),  A [M,Kp] fp16 row-major, B [Kp,Npad] fp16.
// 128x128 CTA tile, BK=128, 256 threads = 8 warps (2x4), warp tile 64x32.
// K pre-padded to mult of 128; scratch tensors fully zero-padded -> no guards.
// OUT=0: ReLU + fp16 store.  OUT=1: fp32 store guarded by Nvalid.
// ---------------------------------------------------------------------------
#define GBM 128
#define GBN 128
#define GBK 128
#define APAD 136   // A smem row stride (halves): 272B rows, conflict-free ldsm
#define BPAD 136   // B smem row stride (halves)
#define A_HALVES (GBM * APAD)                 // 17408
#define B_HALVES (GBK * BPAD)                 // 17408
#define GEMM_SMEM_BYTES ((A_HALVES + B_HALVES) * 2)  // 69632 B

template <int OUT>
__global__ void __launch_bounds__(256, 2)
gemm_fp16(const __half* __restrict__ A, int lda,
          const __half* __restrict__ B, int ldb,
          const float* __restrict__ bias,
          __half* __restrict__ Ch,
          float* __restrict__ Cf, int ldc, int Nvalid,
          int kIters)
{
    extern __shared__ __half sm[];
    __half* sA = sm;
    __half* sB = sA + A_HALVES;

    const int tid  = threadIdx.x;
    const int lane = tid & 31;
    const int wid  = tid >> 5;
    const int warpRow = (wid & 1) * 64;
    const int warpCol = (wid >> 1) * 32;
    const int bm = blockIdx.y * GBM;
    const int bn = blockIdx.x * GBN;

    float acc[4][4][4];
#pragma unroll
    for (int i = 0; i < 4; i++)
#pragma unroll
        for (int j = 0; j < 4; j++)
#pragma unroll
            for (int f = 0; f < 4; f++) acc[i][j][f] = 0.0f;

    // ldmatrix lane addressing
    const int lm  = lane >> 3;
    const int lr  = lane & 7;
    const int aRowOff = (lm & 1) * 8 + lr;
    const int aColOff = (lm >> 1) * 8;
    const int bRowOff = (lm & 1) * 8 + lr;
    const int bColOff = (lm >> 1) * 8;

    for (int kt = 0; kt < kIters; kt++) {
        const int k0 = kt * GBK;

        // A: 128 rows x 128 halves = 2048 uint4; 8/thread.
        // B: 128 rows x 128 halves = 2048 uint4; 8/thread.
#pragma unroll
        for (int v = 0; v < 8; v++) {
            int idx = v * 256 + tid;
            int r  = idx >> 4;
            int c8 = (idx & 15) << 3;
            *(uint4*)(sA + r * APAD + c8) =
                *(const uint4*)(A + (size_t)(bm + r) * lda + k0 + c8);
            *(uint4*)(sB + r * BPAD + c8) =
                *(const uint4*)(B + (size_t)(k0 + r) * ldb + bn + c8);
        }
        __syncthreads();

#pragma unroll
        for (int ks = 0; ks < GBK; ks += 16) {
            // B fragments for this ks
            uint32_t bf[4][2];
#pragma unroll
            for (int ni = 0; ni < 2; ni++) {
                const __half* pb = sB + (ks + bRowOff) * BPAD
                                 + warpCol + ni * 16 + bColOff;
                uint32_t r0, r1, r2, r3;
                ldsm_x4_trans(r0, r1, r2, r3, pb);
                bf[ni * 2 + 0][0] = r0; bf[ni * 2 + 0][1] = r1;
                bf[ni * 2 + 1][0] = r2; bf[ni * 2 + 1][1] = r3;
            }
            // A fragment per mi, then 4 mma
#pragma unroll
            for (int mi = 0; mi < 4; mi++) {
                uint32_t af[4];
                ldsm_x4(af[0], af[1], af[2], af[3],
                        sA + (warpRow + mi * 16 + aRowOff) * APAD + ks + aColOff);
#pragma unroll
                for (int nj = 0; nj < 4; nj++)
                    mma16816(acc[mi][nj], af, bf[nj]);
            }
        }
        __syncthreads();
    }

    // Epilogue
    const int gid = lane >> 2;
    const int tg  = lane & 3;
#pragma unroll
    for (int mi = 0; mi < 4; mi++) {
#pragma unroll
        for (int nj = 0; nj < 4; nj++) {
            int col = bn + warpCol + nj * 8 + tg * 2;
            float bv0 = 0.0f, bv1 = 0.0f;
            if (OUT == 0 || col + 1 < Nvalid) {
                bv0 = bias[col];
                bv1 = bias[col + 1];
            }
#pragma unroll
            for (int half_ = 0; half_ < 2; half_++) {
                int row = bm + warpRow + mi * 16 + gid + half_ * 8;
                float v0 = acc[mi][nj][half_ * 2 + 0] + bv0;
                float v1 = acc[mi][nj][half_ * 2 + 1] + bv1;
                if (OUT == 0) {
                    v0 = fmaxf(v0, 0.0f);
                    v1 = fmaxf(v1, 0.0f);
                    __half2 hp;
                    hp.x = __float2half(v0);
                    hp.y = __float2half(v1);
                    *(__half2*)&Ch[(size_t)row * ldc + col] = hp;
                } else {
                    if (col + 1 < Nvalid) {
                        float2 v; v.x = v0; v.y = v1;
                        *(float2*)&Cf[(size_t)row * ldc + col] = v;
                    }
                }
            }
        }
    }
}

// ---------------------------------------------------------------------------
// Sampler: incremental log-softmax-without-replacement
// ---------------------------------------------------------------------------
__global__ void __launch_bounds__(64)
sampler_kernel(const float* __restrict__ logits,
               const int* __restrict__ idxR, const int* __restrict__ lenR,
               const int* __restrict__ idxS, const int* __restrict__ lenS,
               float* __restrict__ out)
{
    const int b = blockIdx.x;
    const int w = threadIdx.x >> 5;
    const int lane = threadIdx.x & 31;

    const float* lrow = logits + (size_t)b * NACT + w * NHEAD;
    const int* sidx = (w == 0 ? idxR : idxS) + (size_t)b * KSEQ;
    const int slen = (w == 0 ? lenR : lenS)[b];

    float m = -INFINITY;
    for (int i = lane; i < NHEAD; i += 32) m = fmaxf(m, lrow[i]);
#pragma unroll
    for (int off = 16; off > 0; off >>= 1)
        m = fmaxf(m, __shfl_xor_sync(0xFFFFFFFFu, m, off));

    float S1 = 0.0f, S2 = 0.0f;
    for (int i = lane; i < NHEAD; i += 32) {
        float l = lrow[i] - m;
        float e = expf(l);
        S1 += e;
        S2 += l * e;
    }
#pragma unroll
    for (int off = 16; off > 0; off >>= 1) {
        S1 += __shfl_xor_sync(0xFFFFFFFFu, S1, off);
        S2 += __shfl_xor_sync(0xFFFFFFFFu, S2, off);
    }

    __shared__ float sh[4];
    if (lane == 0) {
        float logp = 0.0f, ent = 0.0f;
        for (int t = 0; t < slen; t++) {
            float lS1 = logf(S1);
            ent += lS1 - S2 / S1;
            int id = sidx[t];
            if (id >= 0) {
                float l = lrow[id] - m;
                logp += l - lS1;
                float e = expf(l);
                S1 -= e;
                S2 -= l * e;
            }
        }
        sh[w * 2 + 0] = logp;
        sh[w * 2 + 1] = ent;
    }
    __syncthreads();
    if (threadIdx.x == 0) {
        out[b]         = sh[0] + sh[2];
        out[BATCH + b] = sh[1] + sh[3];
    }
}

// ---------------------------------------------------------------------------
// Launch
// ---------------------------------------------------------------------------
extern "C" void kernel_launch(void* const* d_in, const int* in_sizes, int n_in,
                              void* d_out, int out_size)
{
    const float* state = (const float*)d_in[0];
    const float* W0    = (const float*)d_in[1];
    const float* b0    = (const float*)d_in[2];
    const float* W1    = (const float*)d_in[3];
    const float* b1    = (const float*)d_in[4];
    const float* W2    = (const float*)d_in[5];
    const float* b2    = (const float*)d_in[6];
    const int* seq_idx_R = (const int*)d_in[7];
    const int* seq_len_R = (const int*)d_in[8];
    const int* seq_idx_S = (const int*)d_in[9];
    const int* seq_len_S = (const int*)d_in[10];
    float* out = (float*)d_out;

    __half *S, *Wq0, *Wq1, *Wq2, *H0, *H1;
    float* lg;
    cudaGetSymbolAddress((void**)&S,   g_S);
    cudaGetSymbolAddress((void**)&Wq0, g_W0);
    cudaGetSymbolAddress((void**)&Wq1, g_W1);
    cudaGetSymbolAddress((void**)&Wq2, g_W2);
    cudaGetSymbolAddress((void**)&H0,  g_H0);
    cudaGetSymbolAddress((void**)&H1,  g_H1);
    cudaGetSymbolAddress((void**)&lg,  g_logits);

    cudaFuncSetAttribute(gemm_fp16<0>, cudaFuncAttributeMaxDynamicSharedMemorySize, GEMM_SMEM_BYTES);
    cudaFuncSetAttribute(gemm_fp16<1>, cudaFuncAttributeMaxDynamicSharedMemorySize, GEMM_SMEM_BYTES);

    // Convert + pad to fp16
    pad_half_kernel<<<2048, 256>>>(state, S, BATCH, DIN, BATCH, KP1);
    pad_half_kernel<<<1024, 256>>>(W0, Wq0, DIN, HID, KP1, HID);
    pad_half_kernel<<<1024, 256>>>(W1, Wq1, HID, HID, HID, HID);
    pad_half_kernel<<<1024, 256>>>(W2, Wq2, HID, NACT, HID, NACTP);

    dim3 blk(256);
    dim3 g1(HID / GBN, BATCH / GBM);     // (8, 64)
    dim3 g3(NACTP / GBN, BATCH / GBM);   // (9, 64)

    gemm_fp16<0><<<g1, blk, GEMM_SMEM_BYTES>>>(S,  KP1, Wq0, HID, b0,
                                               H0, nullptr, HID, HID, KP1 / GBK);
    gemm_fp16<0><<<g1, blk, GEMM_SMEM_BYTES>>>(H0, HID, Wq1, HID, b1,
                                               H1, nullptr, HID, HID, HID / GBK);
    gemm_fp16<1><<<g3, blk, GEMM_SMEM_BYTES>>>(H1, HID, Wq2, NACTP, b2,
                                               nullptr, lg, NACT, NACT, HID / GBK);

    sampler_kernel<<<BATCH, 64>>>(lg, seq_idx_R, seq_len_R,
                                  seq_idx_S, seq_len_S, out);
}

// round 11
// speedup vs baseline: 5.5047x; 1.0149x over previous
#include <cuda_runtime.h>
#include <cuda_fp16.h>
#include <math.h>
#include <stdint.h>

// Problem constants
#define BATCH 8192
#define DIN   1025
#define HID   1024
#define NACT  1026
#define NHEAD 513
#define KSEQ  32

// Padded dims
#define KP1   1152   // DIN -> mult of 64 (and 128)
#define NACTP 1152

// ---------------------------------------------------------------------------
// Scratch (allocation-free: __device__ globals)
// ---------------------------------------------------------------------------
__device__ __half g_S [(size_t)BATCH * KP1];
__device__ __half g_W0[(size_t)KP1 * HID];
__device__ __half g_W1[(size_t)HID * HID];
__device__ __half g_W2[(size_t)HID * NACTP];
__device__ __half g_H0[(size_t)BATCH * HID];
__device__ __half g_H1[(size_t)BATCH * HID];
__device__ float  g_logits[(size_t)BATCH * NACT];

// ---------------------------------------------------------------------------
// Pad/convert: fp32 [R,C] -> fp16 [Rpad, Cpad], zero outside [R,C].
// ---------------------------------------------------------------------------
__global__ void pad_half_kernel(const float* __restrict__ src,
                                __half* __restrict__ dst,
                                int R, int C, int Rpad, int Cpad)
{
    size_t total = (size_t)Rpad * Cpad;
    for (size_t idx = (size_t)blockIdx.x * blockDim.x + threadIdx.x;
         idx < total; idx += (size_t)gridDim.x * blockDim.x) {
        int r = (int)(idx / Cpad);
        int c = (int)(idx % Cpad);
        float v = 0.0f;
        if (r < R && c < C) v = src[(size_t)r * C + c];
        dst[idx] = __float2half(v);
    }
}

// ---------------------------------------------------------------------------
// PTX helpers
// ---------------------------------------------------------------------------
__device__ __forceinline__ void ldsm_x4(uint32_t& r0, uint32_t& r1,
                                        uint32_t& r2, uint32_t& r3,
                                        const void* p)
{
    uint32_t a = (uint32_t)__cvta_generic_to_shared(p);
    asm volatile("ldmatrix.sync.aligned.m8n8.x4.shared.b16 {%0,%1,%2,%3}, [%4];"
                 : "=r"(r0), "=r"(r1), "=r"(r2), "=r"(r3) : "r"(a));
}

__device__ __forceinline__ void ldsm_x4_trans(uint32_t& r0, uint32_t& r1,
                                              uint32_t& r2, uint32_t& r3,
                                              const void* p)
{
    uint32_t a = (uint32_t)__cvta_generic_to_shared(p);
    asm volatile("ldmatrix.sync.aligned.m8n8.x4.trans.shared.b16 {%0,%1,%2,%3}, [%4];"
                 : "=r"(r0), "=r"(r1), "=r"(r2), "=r"(r3) : "r"(a));
}

__device__ __forceinline__ void mma16816(float* d, const uint32_t* a, const uint32_t* b)
{
    asm("mma.sync.aligned.m16n8k16.row.col.f32.f16.f16.f32 "
        "{%0,%1,%2,%3}, {%4,%5,%6,%7}, {%8,%9}, {%0,%1,%2,%3};"
        : "+f"(d[0]), "+f"(d[1]), "+f"(d[2]), "+f"(d[3])
        : "r"(a[0]), "r"(a[1]), "r"(a[2]), "r"(a[3]),
          "r"(b[0]), "r"(b[1]));
}

__device__ __forceinline__ void cp16(uint32_t dst, const void* src)
{
    asm volatile("cp.async.cg.shared.global [%0], [%1], 16;"
                 :: "r"(dst), "l"(src));
}
__device__ __forceinline__ void cp_commit() {
    asm volatile("cp.async.commit_group;" ::: "memory");
}
__device__ __forceinline__ void cp_wait1() {
    asm volatile("cp.async.wait_group 1;" ::: "memory");
}

// ---------------------------------------------------------------------------
// fp16 tensor-core GEMM, 2-stage cp.async double buffer AT OCCUPANCY 2.
//   C = act( A @ B + bias ), A [M,Kp] fp16 row-major, B [Kp,Npad] fp16.
// 128x128 CTA tile, BK=64, 256 threads = 8 warps (2x4), warp tile 64x32.
// Stage = 35.8 KB; 2 stages = 71.7 KB/CTA; 2 CTAs/SM = 143 KB (fits 228 KB).
// K pre-padded to mult of 64; scratch tensors fully zero-padded -> no guards.
// ---------------------------------------------------------------------------
#define GBM 128
#define GBN 128
#define GBK 64
#define APAD 72    // A smem row stride (halves): 144B, conflict-free ldsm
#define BPAD 136   // B smem row stride (halves): 272B, conflict-free ldsm
#define A_HALVES (GBM * APAD)                     // 9216
#define B_HALVES (GBK * BPAD)                     // 8704
#define STAGE_HALVES (A_HALVES + B_HALVES)        // 17920 (35840 B)
#define GEMM_SMEM_BYTES (2 * STAGE_HALVES * 2)    // 71680 B

template <int OUT>
__global__ void __launch_bounds__(256, 2)
gemm_fp16(const __half* __restrict__ A, int lda,
          const __half* __restrict__ B, int ldb,
          const float* __restrict__ bias,
          __half* __restrict__ Ch,
          float* __restrict__ Cf, int ldc, int Nvalid,
          int kIters)
{
    extern __shared__ __half sm[];

    const int tid  = threadIdx.x;
    const int lane = tid & 31;
    const int wid  = tid >> 5;
    const int warpRow = (wid & 1) * 64;
    const int warpCol = (wid >> 1) * 32;
    const int bm = blockIdx.y * GBM;
    const int bn = blockIdx.x * GBN;

    const uint32_t sbase = (uint32_t)__cvta_generic_to_shared(sm);

    float acc[4][4][4];
#pragma unroll
    for (int i = 0; i < 4; i++)
#pragma unroll
        for (int j = 0; j < 4; j++)
#pragma unroll
            for (int f = 0; f < 4; f++) acc[i][j][f] = 0.0f;

    // ldmatrix lane addressing
    const int lm  = lane >> 3;
    const int lr  = lane & 7;
    const int aRowOff = (lm & 1) * 8 + lr;
    const int aColOff = (lm >> 1) * 8;
    const int bRowOff = (lm & 1) * 8 + lr;
    const int bColOff = (lm >> 1) * 8;

    // Per-thread cp.async indices: A 1024 vec (8/row), B 1024 vec (16/row); 4 each.
    auto load_stage = [&](int kt, int s) {
        const int k0 = kt * GBK;
        const uint32_t sb = sbase + (uint32_t)(s * STAGE_HALVES) * 2u;
        const uint32_t oB = sb + (uint32_t)A_HALVES * 2u;
#pragma unroll
        for (int v = 0; v < 4; v++) {
            int idx = v * 256 + tid;
            int ar = idx >> 3, ak = (idx & 7) << 3;
            int br = idx >> 4, bn8 = (idx & 15) << 3;
            cp16(sb + (uint32_t)(ar * APAD + ak) * 2u,
                 A + (size_t)(bm + ar) * lda + k0 + ak);
            cp16(oB + (uint32_t)(br * BPAD + bn8) * 2u,
                 B + (size_t)(k0 + br) * ldb + bn + bn8);
        }
    };

    // Prologue: stage 0 in flight.
    load_stage(0, 0);
    cp_commit();

    for (int kt = 0; kt < kIters; kt++) {
        if (kt + 1 < kIters) load_stage(kt + 1, (kt + 1) & 1);
        cp_commit();                 // one group per iteration (possibly empty)
        cp_wait1();                  // chunk kt's group complete
        __syncthreads();

        const int s = kt & 1;
        __half* sA = sm + s * STAGE_HALVES;
        __half* sB = sA + A_HALVES;

#pragma unroll
        for (int ks = 0; ks < GBK; ks += 16) {
            uint32_t bf[4][2];
#pragma unroll
            for (int ni = 0; ni < 2; ni++) {
                const __half* pb = sB + (ks + bRowOff) * BPAD
                                 + warpCol + ni * 16 + bColOff;
                uint32_t r0, r1, r2, r3;
                ldsm_x4_trans(r0, r1, r2, r3, pb);
                bf[ni * 2 + 0][0] = r0; bf[ni * 2 + 0][1] = r1;
                bf[ni * 2 + 1][0] = r2; bf[ni * 2 + 1][1] = r3;
            }
#pragma unroll
            for (int mi = 0; mi < 4; mi++) {
                uint32_t af[4];
                ldsm_x4(af[0], af[1], af[2], af[3],
                        sA + (warpRow + mi * 16 + aRowOff) * APAD + ks + aColOff);
#pragma unroll
                for (int nj = 0; nj < 4; nj++)
                    mma16816(acc[mi][nj], af, bf[nj]);
            }
        }
        __syncthreads();             // stage reads done -> next load may overwrite
    }

    // Epilogue
    const int gid = lane >> 2;
    const int tg  = lane & 3;
#pragma unroll
    for (int mi = 0; mi < 4; mi++) {
#pragma unroll
        for (int nj = 0; nj < 4; nj++) {
            int col = bn + warpCol + nj * 8 + tg * 2;
            float bv0 = 0.0f, bv1 = 0.0f;
            if (OUT == 0 || col + 1 < Nvalid) {
                bv0 = bias[col];
                bv1 = bias[col + 1];
            }
#pragma unroll
            for (int half_ = 0; half_ < 2; half_++) {
                int row = bm + warpRow + mi * 16 + gid + half_ * 8;
                float v0 = acc[mi][nj][half_ * 2 + 0] + bv0;
                float v1 = acc[mi][nj][half_ * 2 + 1] + bv1;
                if (OUT == 0) {
                    v0 = fmaxf(v0, 0.0f);
                    v1 = fmaxf(v1, 0.0f);
                    __half2 hp;
                    hp.x = __float2half(v0);
                    hp.y = __float2half(v1);
                    *(__half2*)&Ch[(size_t)row * ldc + col] = hp;
                } else {
                    if (col + 1 < Nvalid) {
                        float2 v; v.x = v0; v.y = v1;
                        *(float2*)&Cf[(size_t)row * ldc + col] = v;
                    }
                }
            }
        }
    }
}

// ---------------------------------------------------------------------------
// Sampler: incremental log-softmax-without-replacement
// ---------------------------------------------------------------------------
__global__ void __launch_bounds__(64)
sampler_kernel(const float* __restrict__ logits,
               const int* __restrict__ idxR, const int* __restrict__ lenR,
               const int* __restrict__ idxS, const int* __restrict__ lenS,
               float* __restrict__ out)
{
    const int b = blockIdx.x;
    const int w = threadIdx.x >> 5;
    const int lane = threadIdx.x & 31;

    const float* lrow = logits + (size_t)b * NACT + w * NHEAD;
    const int* sidx = (w == 0 ? idxR : idxS) + (size_t)b * KSEQ;
    const int slen = (w == 0 ? lenR : lenS)[b];

    float m = -INFINITY;
    for (int i = lane; i < NHEAD; i += 32) m = fmaxf(m, lrow[i]);
#pragma unroll
    for (int off = 16; off > 0; off >>= 1)
        m = fmaxf(m, __shfl_xor_sync(0xFFFFFFFFu, m, off));

    float S1 = 0.0f, S2 = 0.0f;
    for (int i = lane; i < NHEAD; i += 32) {
        float l = lrow[i] - m;
        float e = expf(l);
        S1 += e;
        S2 += l * e;
    }
#pragma unroll
    for (int off = 16; off > 0; off >>= 1) {
        S1 += __shfl_xor_sync(0xFFFFFFFFu, S1, off);
        S2 += __shfl_xor_sync(0xFFFFFFFFu, S2, off);
    }

    __shared__ float sh[4];
    if (lane == 0) {
        float logp = 0.0f, ent = 0.0f;
        for (int t = 0; t < slen; t++) {
            float lS1 = logf(S1);
            ent += lS1 - S2 / S1;
            int id = sidx[t];
            if (id >= 0) {
                float l = lrow[id] - m;
                logp += l - lS1;
                float e = expf(l);
                S1 -= e;
                S2 -= l * e;
            }
        }
        sh[w * 2 + 0] = logp;
        sh[w * 2 + 1] = ent;
    }
    __syncthreads();
    if (threadIdx.x == 0) {
        out[b]         = sh[0] + sh[2];
        out[BATCH + b] = sh[1] + sh[3];
    }
}

// ---------------------------------------------------------------------------
// Launch
// ---------------------------------------------------------------------------
extern "C" void kernel_launch(void* const* d_in, const int* in_sizes, int n_in,
                              void* d_out, int out_size)
{
    const float* state = (const float*)d_in[0];
    const float* W0    = (const float*)d_in[1];
    const float* b0    = (const float*)d_in[2];
    const float* W1    = (const float*)d_in[3];
    const float* b1    = (const float*)d_in[4];
    const float* W2    = (const float*)d_in[5];
    const float* b2    = (const float*)d_in[6];
    const int* seq_idx_R = (const int*)d_in[7];
    const int* seq_len_R = (const int*)d_in[8];
    const int* seq_idx_S = (const int*)d_in[9];
    const int* seq_len_S = (const int*)d_in[10];
    float* out = (float*)d_out;

    __half *S, *Wq0, *Wq1, *Wq2, *H0, *H1;
    float* lg;
    cudaGetSymbolAddress((void**)&S,   g_S);
    cudaGetSymbolAddress((void**)&Wq0, g_W0);
    cudaGetSymbolAddress((void**)&Wq1, g_W1);
    cudaGetSymbolAddress((void**)&Wq2, g_W2);
    cudaGetSymbolAddress((void**)&H0,  g_H0);
    cudaGetSymbolAddress((void**)&H1,  g_H1);
    cudaGetSymbolAddress((void**)&lg,  g_logits);

    cudaFuncSetAttribute(gemm_fp16<0>, cudaFuncAttributeMaxDynamicSharedMemorySize, GEMM_SMEM_BYTES);
    cudaFuncSetAttribute(gemm_fp16<1>, cudaFuncAttributeMaxDynamicSharedMemorySize, GEMM_SMEM_BYTES);

    // Convert + pad to fp16
    pad_half_kernel<<<2048, 256>>>(state, S, BATCH, DIN, BATCH, KP1);
    pad_half_kernel<<<1024, 256>>>(W0, Wq0, DIN, HID, KP1, HID);
    pad_half_kernel<<<1024, 256>>>(W1, Wq1, HID, HID, HID, HID);
    pad_half_kernel<<<1024, 256>>>(W2, Wq2, HID, NACT, HID, NACTP);

    dim3 blk(256);
    dim3 g1(HID / GBN, BATCH / GBM);     // (8, 64)
    dim3 g3(NACTP / GBN, BATCH / GBM);   // (9, 64)

    gemm_fp16<0><<<g1, blk, GEMM_SMEM_BYTES>>>(S,  KP1, Wq0, HID, b0,
                                               H0, nullptr, HID, HID, KP1 / GBK);
    gemm_fp16<0><<<g1, blk, GEMM_SMEM_BYTES>>>(H0, HID, Wq1, HID, b1,
                                               H1, nullptr, HID, HID, HID / GBK);
    gemm_fp16<1><<<g3, blk, GEMM_SMEM_BYTES>>>(H1, HID, Wq2, NACTP, b2,
                                               nullptr, lg, NACT, NACT, HID / GBK);

    sampler_kernel<<<BATCH, 64>>>(lg, seq_idx_R, seq_len_R,
                                  seq_idx_S, seq_len_S, out);
}